// round 14
// baseline (speedup 1.0000x reference)
#include <cuda_runtime.h>

#define NN      8000
#define NFEATD  512
#define NHID    128
#define NCLS    64
#define CAP     128
#define NCHUNK  2000   // NN/4 uint4 chunks per adj row
#define NBLK    296    // total resident blocks (2/SM * 148)
#define NGEMM   125    // GEMM tile blocks (join scan afterwards)
#define ROWGRAB 8      // rows per steal

// ---- persistent scratch (no allocs allowed) ----
__device__ float g_h[NN * NHID];        // h = relu(xW0+b0) (== h0)
__device__ float g_li0[NN * NHID];
__device__ float g_li1[NN * NHID];
__device__ float g_yhat[NN * NCLS];
__device__ float g_w[NN * CAP];         // normalized edge weights (incl. 0.9/L1)
__device__ int   g_cols[NN * CAP];
__device__ int   g_nnz[NN];
__device__ int   g_ctr;                 // steal counter; ends every launch at 0

// ============================================================
// k_main: blocks [0,NGEMM) = GEMM tile + fused pseudo/inject/softmax
// epilogue, then join scan. Blocks [NGEMM,NBLK) = CSR scan workers.
// ============================================================
#define SM_AS   (2 * 16 * 65)     // 2080
#define SM_BS   (2 * 16 * 128)    // 4096
#define SM_H    (64 * 129)        // 8256  (h tile, stride 129: conflict-free)

__global__ void __launch_bounds__(256, 2) k_main(
        const float* __restrict__ x,  const float* __restrict__ W0,
        const float* __restrict__ b0, const float* __restrict__ adj,
        const float* __restrict__ W1, const float* __restrict__ b1,
        const int* __restrict__ idx,  const float* __restrict__ y,
        float* __restrict__ out_pseudo) {
    __shared__ __align__(16) float smem[SM_H];   // >= SM_AS+SM_BS
    __shared__ int   scnt[64];
    __shared__ float pm[8][4], ps[8][4];
    __shared__ int   s_row, s_cnt;

    const int tid = threadIdx.x;

    if (blockIdx.x < NGEMM) {
        // ---------- GEMM: 64x128 tile, BK=16, 256 thr, 4x8 micro ----------
        const int tx = tid & 15, ty = tid >> 4;
        const int br = blockIdx.x * 64;
        float* As = smem;
        float* Bs = smem + SM_AS;

        const int ar = tid >> 2;
        const int ak = (tid & 3) * 4;
        const int bk = tid >> 5;
        const int bc = (tid & 31) * 4;

        float4 a_r, b_r0, b_r1;
        a_r  = *(const float4*)&x[(size_t)(br + ar) * NFEATD + ak];
        b_r0 = *(const float4*)&W0[(size_t)(bk)     * NHID + bc];
        b_r1 = *(const float4*)&W0[(size_t)(bk + 8) * NHID + bc];
        As[(0 + ak + 0) * 65 + ar] = a_r.x;
        As[(0 + ak + 1) * 65 + ar] = a_r.y;
        As[(0 + ak + 2) * 65 + ar] = a_r.z;
        As[(0 + ak + 3) * 65 + ar] = a_r.w;
        *(float4*)&Bs[(0 + bk)     * 128 + bc] = b_r0;
        *(float4*)&Bs[(0 + bk + 8) * 128 + bc] = b_r1;
        __syncthreads();

        float acc[4][8];
#pragma unroll
        for (int i = 0; i < 4; i++)
#pragma unroll
            for (int j = 0; j < 8; j++) acc[i][j] = 0.f;

        for (int kt = 0; kt < 32; kt++) {
            const int cur = (kt & 1) * 16, nxt = ((kt + 1) & 1) * 16;
            if (kt < 31) {
                const int k0 = (kt + 1) * 16;
                a_r  = *(const float4*)&x[(size_t)(br + ar) * NFEATD + k0 + ak];
                b_r0 = *(const float4*)&W0[(size_t)(k0 + bk)     * NHID + bc];
                b_r1 = *(const float4*)&W0[(size_t)(k0 + bk + 8) * NHID + bc];
            }
#pragma unroll
            for (int kk = 0; kk < 16; kk++) {
                float ra[4], rb[8];
#pragma unroll
                for (int i = 0; i < 4; i++) ra[i] = As[(cur + kk) * 65 + ty * 4 + i];
                *(float4*)&rb[0] = *(float4*)&Bs[(cur + kk) * 128 + tx * 8];
                *(float4*)&rb[4] = *(float4*)&Bs[(cur + kk) * 128 + tx * 8 + 4];
#pragma unroll
                for (int i = 0; i < 4; i++)
#pragma unroll
                    for (int j = 0; j < 8; j++) acc[i][j] += ra[i] * rb[j];
            }
            if (kt < 31) {
                As[(nxt + ak + 0) * 65 + ar] = a_r.x;
                As[(nxt + ak + 1) * 65 + ar] = a_r.y;
                As[(nxt + ak + 2) * 65 + ar] = a_r.z;
                As[(nxt + ak + 3) * 65 + ar] = a_r.w;
                *(float4*)&Bs[(nxt + bk)     * 128 + bc] = b_r0;
                *(float4*)&Bs[(nxt + bk + 8) * 128 + bc] = b_r1;
            }
            __syncthreads();
        }

        const float4 bv0 = *(const float4*)&b0[tx * 8];
        const float4 bv1 = *(const float4*)&b0[tx * 8 + 4];
#pragma unroll
        for (int i = 0; i < 4; i++) {
            const int r = br + ty * 4 + i;
            float4 o0, o1;
            o0.x = fmaxf(acc[i][0] + bv0.x, 0.f);
            o0.y = fmaxf(acc[i][1] + bv0.y, 0.f);
            o0.z = fmaxf(acc[i][2] + bv0.z, 0.f);
            o0.w = fmaxf(acc[i][3] + bv0.w, 0.f);
            o1.x = fmaxf(acc[i][4] + bv1.x, 0.f);
            o1.y = fmaxf(acc[i][5] + bv1.y, 0.f);
            o1.z = fmaxf(acc[i][6] + bv1.z, 0.f);
            o1.w = fmaxf(acc[i][7] + bv1.w, 0.f);
            *(float4*)&g_h[(size_t)r * NHID + tx * 8]       = o0;
            *(float4*)&g_h[(size_t)r * NHID + tx * 8 + 4]   = o1;
            *(float4*)&g_li0[(size_t)r * NHID + tx * 8]     = o0;
            *(float4*)&g_li0[(size_t)r * NHID + tx * 8 + 4] = o1;
            // stage h tile into smem (stride 129, conflict-free reads)
            float* hr = &smem[(ty * 4 + i) * 129 + tx * 8];
            hr[0] = o0.x; hr[1] = o0.y; hr[2] = o0.z; hr[3] = o0.w;
            hr[4] = o1.x; hr[5] = o1.y; hr[6] = o1.z; hr[7] = o1.w;
        }
        if (tid < 64) scnt[tid] = 0;
        __syncthreads();

        // ---------- fused pseudo + inject + softmax (64 rows) ----------
        for (int e = tid; e < 500; e += 256) {
            const int v = idx[e] - br;
            if ((unsigned)v < 64u) atomicAdd(&scnt[v], 1);
        }
        __syncthreads();

        const int sub = tid >> 6;       // 4 sub-blocks of 64 threads
        const int c   = tid & 63;       // class
        const int w   = tid >> 5;       // warp (0..7), partner w^1
        const float bb1 = b1[c];
#pragma unroll
        for (int it = 0; it < 4; it++) {
            const int r0 = sub * 16 + it * 4;
            const float* h0 = &smem[(r0 + 0) * 129];
            const float* h1 = &smem[(r0 + 1) * 129];
            const float* h2 = &smem[(r0 + 2) * 129];
            const float* h3 = &smem[(r0 + 3) * 129];
            float p0 = bb1, p1 = bb1, p2 = bb1, p3 = bb1;
#pragma unroll 8
            for (int k = 0; k < NHID; k++) {
                const float wv = W1[k * NCLS + c];
                p0 += h0[k] * wv; p1 += h1[k] * wv;
                p2 += h2[k] * wv; p3 += h3[k] * wv;
            }
            const int c0 = scnt[r0 + 0], c1 = scnt[r0 + 1];
            const int c2 = scnt[r0 + 2], c3 = scnt[r0 + 3];
            if (c0) p0 += 0.1f * c0 * y[(size_t)(br + r0 + 0) * NCLS + c];
            if (c1) p1 += 0.1f * c1 * y[(size_t)(br + r0 + 1) * NCLS + c];
            if (c2) p2 += 0.1f * c2 * y[(size_t)(br + r0 + 2) * NCLS + c];
            if (c3) p3 += 0.1f * c3 * y[(size_t)(br + r0 + 3) * NCLS + c];
            out_pseudo[(size_t)(br + r0 + 0) * NCLS + c] = p0;
            out_pseudo[(size_t)(br + r0 + 1) * NCLS + c] = p1;
            out_pseudo[(size_t)(br + r0 + 2) * NCLS + c] = p2;
            out_pseudo[(size_t)(br + r0 + 3) * NCLS + c] = p3;

            // softmax: butterfly within warp (32 classes), combine pairs via smem
            float m0 = p0, m1 = p1, m2 = p2, m3 = p3;
#pragma unroll
            for (int o = 16; o; o >>= 1) {
                m0 = fmaxf(m0, __shfl_xor_sync(~0u, m0, o));
                m1 = fmaxf(m1, __shfl_xor_sync(~0u, m1, o));
                m2 = fmaxf(m2, __shfl_xor_sync(~0u, m2, o));
                m3 = fmaxf(m3, __shfl_xor_sync(~0u, m3, o));
            }
            if ((tid & 31) == 0) { pm[w][0] = m0; pm[w][1] = m1; pm[w][2] = m2; pm[w][3] = m3; }
            __syncthreads();
            m0 = fmaxf(pm[w][0], pm[w ^ 1][0]);
            m1 = fmaxf(pm[w][1], pm[w ^ 1][1]);
            m2 = fmaxf(pm[w][2], pm[w ^ 1][2]);
            m3 = fmaxf(pm[w][3], pm[w ^ 1][3]);
            const float e0 = expf(p0 - m0), e1 = expf(p1 - m1);
            const float e2 = expf(p2 - m2), e3 = expf(p3 - m3);
            float s0 = e0, s1 = e1, s2 = e2, s3 = e3;
#pragma unroll
            for (int o = 16; o; o >>= 1) {
                s0 += __shfl_xor_sync(~0u, s0, o);
                s1 += __shfl_xor_sync(~0u, s1, o);
                s2 += __shfl_xor_sync(~0u, s2, o);
                s3 += __shfl_xor_sync(~0u, s3, o);
            }
            if ((tid & 31) == 0) { ps[w][0] = s0; ps[w][1] = s1; ps[w][2] = s2; ps[w][3] = s3; }
            __syncthreads();
            s0 = ps[w][0] + ps[w ^ 1][0];
            s1 = ps[w][1] + ps[w ^ 1][1];
            s2 = ps[w][2] + ps[w ^ 1][2];
            s3 = ps[w][3] + ps[w ^ 1][3];
            g_yhat[(size_t)(br + r0 + 0) * NCLS + c] = e0 / s0;
            g_yhat[(size_t)(br + r0 + 1) * NCLS + c] = e1 / s1;
            g_yhat[(size_t)(br + r0 + 2) * NCLS + c] = e2 / s2;
            g_yhat[(size_t)(br + r0 + 3) * NCLS + c] = e3 / s3;
        }
        __syncthreads();   // smem reuse barrier before scan phase
    }

    // ---------- CSR scan: all blocks steal 8-row chunks ----------
    for (;;) {
        if (tid == 0) s_row = atomicAdd(&g_ctr, ROWGRAB);
        __syncthreads();
        const int row0 = s_row;
        if (row0 >= NN) break;
        const int rend = (row0 + ROWGRAB < NN) ? row0 + ROWGRAB : NN;
        for (int i = row0; i < rend; i++) {
            if (tid == 0) s_cnt = 0;
            __syncthreads();
            const uint4* row4 = (const uint4*)(adj + (size_t)i * NN);
            uint4 cc[8];
#pragma unroll
            for (int k = 0; k < 7; k++) cc[k] = row4[tid + 256 * k];
            {
                const int i7 = tid + 256 * 7;
                if (i7 < NCHUNK) cc[7] = row4[i7];
                else             cc[7] = make_uint4(0u, 0u, 0u, 0u);
            }
            unsigned allor = 0u;
#pragma unroll
            for (int k = 0; k < 8; k++)
                allor |= (cc[k].x | cc[k].y) | (cc[k].z | cc[k].w);
            if (allor) {
#pragma unroll
                for (int k = 0; k < 8; k++) {
                    const unsigned oc = (cc[k].x | cc[k].y) | (cc[k].z | cc[k].w);
                    if (oc) {
                        const int base = (tid + 256 * k) * 4;
                        if (cc[k].x) { int p = atomicAdd(&s_cnt, 1); if (p < CAP) g_cols[i * CAP + p] = base + 0; }
                        if (cc[k].y) { int p = atomicAdd(&s_cnt, 1); if (p < CAP) g_cols[i * CAP + p] = base + 1; }
                        if (cc[k].z) { int p = atomicAdd(&s_cnt, 1); if (p < CAP) g_cols[i * CAP + p] = base + 2; }
                        if (cc[k].w) { int p = atomicAdd(&s_cnt, 1); if (p < CAP) g_cols[i * CAP + p] = base + 3; }
                    }
                }
            }
            __syncthreads();
            if (tid == 0) g_nnz[i] = (s_cnt < CAP) ? s_cnt : CAP;
        }
    }
}

// ============================================================
// Layer 1, fused (warp per row, 4 rows / 128-thr block):
//  A: w_e = dot(yhat_i,yhat_j) (unroll-4), normalize (0.9/L1) -> smem + g_w
//  B: li1 = L2norm( sum w_e*li0[j] + 0.1*h0 )   (unroll-4 gather)
// ============================================================
__global__ void __launch_bounds__(128) k_prop1() {
    const int w    = threadIdx.x >> 5;
    const int lane = threadIdx.x & 31;
    const int i    = blockIdx.x * 4 + w;
    __shared__ int   sj[4][CAP];
    __shared__ float sw[4][CAP];

    const int nnz = g_nnz[i];
    int* jrow = sj[w];
    float* wrow = sw[w];
    for (int e = lane; e < nnz; e += 32) jrow[e] = g_cols[i * CAP + e];
    __syncwarp();

    // --- phase A: edge dots (4 gathers in flight) ---
    const float2 ya = ((const float2*)(g_yhat + (size_t)i * NCLS))[lane];
    int e = 0;
    for (; e + 4 <= nnz; e += 4) {
        const float2 v0 = ((const float2*)(g_yhat + (size_t)jrow[e]     * NCLS))[lane];
        const float2 v1 = ((const float2*)(g_yhat + (size_t)jrow[e + 1] * NCLS))[lane];
        const float2 v2 = ((const float2*)(g_yhat + (size_t)jrow[e + 2] * NCLS))[lane];
        const float2 v3 = ((const float2*)(g_yhat + (size_t)jrow[e + 3] * NCLS))[lane];
        float p0 = ya.x * v0.x + ya.y * v0.y;
        float p1 = ya.x * v1.x + ya.y * v1.y;
        float p2 = ya.x * v2.x + ya.y * v2.y;
        float p3 = ya.x * v3.x + ya.y * v3.y;
#pragma unroll
        for (int o = 16; o; o >>= 1) {
            p0 += __shfl_xor_sync(~0u, p0, o);
            p1 += __shfl_xor_sync(~0u, p1, o);
            p2 += __shfl_xor_sync(~0u, p2, o);
            p3 += __shfl_xor_sync(~0u, p3, o);
        }
        if (lane == 0) { wrow[e] = p0; wrow[e + 1] = p1; wrow[e + 2] = p2; wrow[e + 3] = p3; }
    }
    for (; e < nnz; e++) {
        const float2 v0 = ((const float2*)(g_yhat + (size_t)jrow[e] * NCLS))[lane];
        float p0 = ya.x * v0.x + ya.y * v0.y;
#pragma unroll
        for (int o = 16; o; o >>= 1) p0 += __shfl_xor_sync(~0u, p0, o);
        if (lane == 0) wrow[e] = p0;
    }
    __syncwarp();
    float s = 0.f;
    for (int q = lane; q < nnz; q += 32) s += wrow[q];
#pragma unroll
    for (int o = 16; o; o >>= 1) s += __shfl_xor_sync(~0u, s, o);
    const float scale = 0.9f / fmaxf(s, 1e-12f);
    for (int q = lane; q < nnz; q += 32) {
        const float v = wrow[q] * scale;
        wrow[q] = v;
        g_w[i * CAP + q] = v;        // reused by layer 2
    }
    __syncwarp();

    // --- phase B: gather li0 -> li1 ---
    const float4 h4 = ((const float4*)(g_h + (size_t)i * NHID))[lane];
    float4 A0 = make_float4(0.1f * h4.x, 0.1f * h4.y, 0.1f * h4.z, 0.1f * h4.w);
    float4 A1 = make_float4(0.f, 0.f, 0.f, 0.f);
    float4 A2 = make_float4(0.f, 0.f, 0.f, 0.f);
    float4 A3 = make_float4(0.f, 0.f, 0.f, 0.f);
    e = 0;
    for (; e + 4 <= nnz; e += 4) {
        const float w0 = wrow[e],     w1 = wrow[e + 1];
        const float w2 = wrow[e + 2], w3 = wrow[e + 3];
        const float4 v0 = ((const float4*)(g_li0 + (size_t)jrow[e]     * NHID))[lane];
        const float4 v1 = ((const float4*)(g_li0 + (size_t)jrow[e + 1] * NHID))[lane];
        const float4 v2 = ((const float4*)(g_li0 + (size_t)jrow[e + 2] * NHID))[lane];
        const float4 v3 = ((const float4*)(g_li0 + (size_t)jrow[e + 3] * NHID))[lane];
        A0.x += w0 * v0.x; A0.y += w0 * v0.y; A0.z += w0 * v0.z; A0.w += w0 * v0.w;
        A1.x += w1 * v1.x; A1.y += w1 * v1.y; A1.z += w1 * v1.z; A1.w += w1 * v1.w;
        A2.x += w2 * v2.x; A2.y += w2 * v2.y; A2.z += w2 * v2.z; A2.w += w2 * v2.w;
        A3.x += w3 * v3.x; A3.y += w3 * v3.y; A3.z += w3 * v3.z; A3.w += w3 * v3.w;
    }
    for (; e < nnz; e++) {
        const float w0 = wrow[e];
        const float4 v0 = ((const float4*)(g_li0 + (size_t)jrow[e] * NHID))[lane];
        A0.x += w0 * v0.x; A0.y += w0 * v0.y; A0.z += w0 * v0.z; A0.w += w0 * v0.w;
    }
    float4 acc = make_float4(A0.x + A1.x + A2.x + A3.x, A0.y + A1.y + A2.y + A3.y,
                             A0.z + A1.z + A2.z + A3.z, A0.w + A1.w + A2.w + A3.w);
    float sq = acc.x * acc.x + acc.y * acc.y + acc.z * acc.z + acc.w * acc.w;
#pragma unroll
    for (int o = 16; o; o >>= 1) sq += __shfl_xor_sync(~0u, sq, o);
    const float inv = 1.f / fmaxf(sqrtf(sq), 1e-12f);
    acc.x *= inv; acc.y *= inv; acc.z *= inv; acc.w *= inv;
    ((float4*)(g_li1 + (size_t)i * NHID))[lane] = acc;
}

// ============================================================
// Layer 2 gather + fused out = log_softmax(li @ W2 + b2).
// Warp per row, 4 rows / 128-thr block. li never hits DRAM.
// Last duty: reset g_ctr for the next replay.
// ============================================================
__global__ void __launch_bounds__(128) k_gather_out(
        const float* __restrict__ W2, const float* __restrict__ b2,
        float* __restrict__ out) {
    const int w    = threadIdx.x >> 5;
    const int lane = threadIdx.x & 31;
    const int i    = blockIdx.x * 4 + w;
    __shared__ float sli[4][132];   // 16B-aligned rows, broadcast reads
    const int nnz  = g_nnz[i];
    const int*   __restrict__ cols = &g_cols[i * CAP];
    const float* __restrict__ wts  = &g_w[i * CAP];

    const float4 h4 = ((const float4*)(g_h + (size_t)i * NHID))[lane];
    float4 A0 = make_float4(0.1f * h4.x, 0.1f * h4.y, 0.1f * h4.z, 0.1f * h4.w);
    float4 A1 = make_float4(0.f, 0.f, 0.f, 0.f);
    float4 A2 = make_float4(0.f, 0.f, 0.f, 0.f);
    float4 A3 = make_float4(0.f, 0.f, 0.f, 0.f);
    int e = 0;
    for (; e + 4 <= nnz; e += 4) {
        const int j0 = cols[e], j1 = cols[e + 1], j2 = cols[e + 2], j3 = cols[e + 3];
        const float w0 = wts[e], w1 = wts[e + 1], w2 = wts[e + 2], w3 = wts[e + 3];
        const float4 v0 = ((const float4*)(g_li1 + (size_t)j0 * NHID))[lane];
        const float4 v1 = ((const float4*)(g_li1 + (size_t)j1 * NHID))[lane];
        const float4 v2 = ((const float4*)(g_li1 + (size_t)j2 * NHID))[lane];
        const float4 v3 = ((const float4*)(g_li1 + (size_t)j3 * NHID))[lane];
        A0.x += w0 * v0.x; A0.y += w0 * v0.y; A0.z += w0 * v0.z; A0.w += w0 * v0.w;
        A1.x += w1 * v1.x; A1.y += w1 * v1.y; A1.z += w1 * v1.z; A1.w += w1 * v1.w;
        A2.x += w2 * v2.x; A2.y += w2 * v2.y; A2.z += w2 * v2.z; A2.w += w2 * v2.w;
        A3.x += w3 * v3.x; A3.y += w3 * v3.y; A3.z += w3 * v3.z; A3.w += w3 * v3.w;
    }
    for (; e < nnz; e++) {
        const float w0 = wts[e];
        const float4 v0 = ((const float4*)(g_li1 + (size_t)cols[e] * NHID))[lane];
        A0.x += w0 * v0.x; A0.y += w0 * v0.y; A0.z += w0 * v0.z; A0.w += w0 * v0.w;
    }
    float4 acc = make_float4(A0.x + A1.x + A2.x + A3.x, A0.y + A1.y + A2.y + A3.y,
                             A0.z + A1.z + A2.z + A3.z, A0.w + A1.w + A2.w + A3.w);
    float sq = acc.x * acc.x + acc.y * acc.y + acc.z * acc.z + acc.w * acc.w;
#pragma unroll
    for (int o = 16; o; o >>= 1) sq += __shfl_xor_sync(~0u, sq, o);
    const float inv = 1.f / fmaxf(sqrtf(sq), 1e-12f);
    acc.x *= inv; acc.y *= inv; acc.z *= inv; acc.w *= inv;

    // stage li row in smem; W2 GEMV via broadcast reads
    *(float4*)&sli[w][lane * 4] = acc;
    __syncwarp();
    float v0 = b2[lane], v1 = b2[lane + 32];
#pragma unroll 4
    for (int k = 0; k < NHID; k++) {
        const float lv = sli[w][k];
        v0 += lv * W2[k * NCLS + lane];
        v1 += lv * W2[k * NCLS + lane + 32];
    }
    float m = fmaxf(v0, v1);
#pragma unroll
    for (int o = 16; o; o >>= 1) m = fmaxf(m, __shfl_xor_sync(~0u, m, o));
    float sm = expf(v0 - m) + expf(v1 - m);
#pragma unroll
    for (int o = 16; o; o >>= 1) sm += __shfl_xor_sync(~0u, sm, o);
    const float ls = logf(sm);
    out[(size_t)i * NCLS + lane]      = v0 - m - ls;
    out[(size_t)i * NCLS + lane + 32] = v1 - m - ls;

    if (blockIdx.x == 0 && threadIdx.x == 0) g_ctr = 0;   // replay-safe reset
}

// ============================================================
extern "C" void kernel_launch(void* const* d_in, const int* in_sizes, int n_in,
                              void* d_out, int out_size) {
    const float* x   = (const float*)d_in[0];
    const float* adj = (const float*)d_in[1];
    const float* y   = (const float*)d_in[2];
    const int*   idx = (const int*)  d_in[3];
    const float* W0  = (const float*)d_in[4];
    const float* b0  = (const float*)d_in[5];
    const float* W1  = (const float*)d_in[6];
    const float* b1  = (const float*)d_in[7];
    const float* W2  = (const float*)d_in[8];
    const float* b2  = (const float*)d_in[9];
    (void)in_sizes; (void)n_in; (void)out_size;

    float* out_logsm  = (float*)d_out;                       // [8000,64]
    float* out_pseudo = (float*)d_out + (size_t)NN * NCLS;   // [8000,64]

    k_main<<<NBLK, 256>>>(x, W0, b0, adj, W1, b1, idx, y, out_pseudo);
    k_prop1<<<NN / 4, 128>>>();                  // weights + li0 -> li1
    k_gather_out<<<NN / 4, 128>>>(W2, b2, out_logsm);  // li1 -> out (+ctr reset)
}

// round 15
// speedup vs baseline: 1.2694x; 1.2694x over previous
#include <cuda_runtime.h>

#define NN      8000
#define NFEATD  512
#define NHID    128
#define NCLS    64
#define CAP     128
#define NCHUNK  2000   // NN/4 uint4 chunks per adj row
#define NBLK    444    // 3 blocks/SM * 148 SMs
#define NGEMM   125    // GEMM tile blocks (join scan afterwards)

// ---- persistent scratch (no allocs allowed) ----
__device__ float g_h[NN * NHID];        // h = relu(xW0+b0) (== h0)
__device__ float g_li0[NN * NHID];
__device__ float g_li1[NN * NHID];
__device__ float g_yhat[NN * NCLS];
__device__ float g_w[NN * CAP];         // normalized edge weights (incl. 0.9/L1)
__device__ int   g_cols[NN * CAP];
__device__ int   g_nnz[NN];
__device__ int   g_ctr;                 // row-steal counter; ends every launch at 0

// ============================================================
// k_main: blocks [0,NGEMM) do one GEMM tile, then join the scan.
// Scan = warp-autonomous: each warp steals one adj row, streams it
// with 8 outstanding uint4 loads, compacts cols via ballot/popc.
// No __syncthreads, no smem in the scan path.
// ============================================================
#define SM_AS   (2 * 16 * 65)
#define SM_BS   (2 * 16 * 128)

__global__ void __launch_bounds__(256, 3) k_main(
        const float* __restrict__ x,  const float* __restrict__ W0,
        const float* __restrict__ b0, const float* __restrict__ adj) {
    __shared__ __align__(16) float smem[SM_AS + SM_BS];

    if (blockIdx.x < NGEMM) {
        // ---------- GEMM: 64x128 tile, BK=16, 256 thr, 4x8 micro ----------
        const int tid = threadIdx.x;
        const int tx = tid & 15, ty = tid >> 4;
        const int br = blockIdx.x * 64;
        float* As = smem;
        float* Bs = smem + SM_AS;

        const int ar = tid >> 2;
        const int ak = (tid & 3) * 4;
        const int bk = tid >> 5;
        const int bc = (tid & 31) * 4;

        float4 a_r, b_r0, b_r1;
        a_r  = *(const float4*)&x[(size_t)(br + ar) * NFEATD + ak];
        b_r0 = *(const float4*)&W0[(size_t)(bk)     * NHID + bc];
        b_r1 = *(const float4*)&W0[(size_t)(bk + 8) * NHID + bc];
        As[(0 + ak + 0) * 65 + ar] = a_r.x;
        As[(0 + ak + 1) * 65 + ar] = a_r.y;
        As[(0 + ak + 2) * 65 + ar] = a_r.z;
        As[(0 + ak + 3) * 65 + ar] = a_r.w;
        *(float4*)&Bs[(0 + bk)     * 128 + bc] = b_r0;
        *(float4*)&Bs[(0 + bk + 8) * 128 + bc] = b_r1;
        __syncthreads();

        float acc[4][8];
#pragma unroll
        for (int i = 0; i < 4; i++)
#pragma unroll
            for (int j = 0; j < 8; j++) acc[i][j] = 0.f;

        for (int kt = 0; kt < 32; kt++) {
            const int cur = (kt & 1) * 16, nxt = ((kt + 1) & 1) * 16;
            if (kt < 31) {
                const int k0 = (kt + 1) * 16;
                a_r  = *(const float4*)&x[(size_t)(br + ar) * NFEATD + k0 + ak];
                b_r0 = *(const float4*)&W0[(size_t)(k0 + bk)     * NHID + bc];
                b_r1 = *(const float4*)&W0[(size_t)(k0 + bk + 8) * NHID + bc];
            }
#pragma unroll
            for (int kk = 0; kk < 16; kk++) {
                float ra[4], rb[8];
#pragma unroll
                for (int i = 0; i < 4; i++) ra[i] = As[(cur + kk) * 65 + ty * 4 + i];
                *(float4*)&rb[0] = *(float4*)&Bs[(cur + kk) * 128 + tx * 8];
                *(float4*)&rb[4] = *(float4*)&Bs[(cur + kk) * 128 + tx * 8 + 4];
#pragma unroll
                for (int i = 0; i < 4; i++)
#pragma unroll
                    for (int j = 0; j < 8; j++) acc[i][j] += ra[i] * rb[j];
            }
            if (kt < 31) {
                As[(nxt + ak + 0) * 65 + ar] = a_r.x;
                As[(nxt + ak + 1) * 65 + ar] = a_r.y;
                As[(nxt + ak + 2) * 65 + ar] = a_r.z;
                As[(nxt + ak + 3) * 65 + ar] = a_r.w;
                *(float4*)&Bs[(nxt + bk)     * 128 + bc] = b_r0;
                *(float4*)&Bs[(nxt + bk + 8) * 128 + bc] = b_r1;
            }
            __syncthreads();
        }

        const float4 bv0 = *(const float4*)&b0[tx * 8];
        const float4 bv1 = *(const float4*)&b0[tx * 8 + 4];
#pragma unroll
        for (int i = 0; i < 4; i++) {
            const int r = br + ty * 4 + i;
            float4 o0, o1;
            o0.x = fmaxf(acc[i][0] + bv0.x, 0.f);
            o0.y = fmaxf(acc[i][1] + bv0.y, 0.f);
            o0.z = fmaxf(acc[i][2] + bv0.z, 0.f);
            o0.w = fmaxf(acc[i][3] + bv0.w, 0.f);
            o1.x = fmaxf(acc[i][4] + bv1.x, 0.f);
            o1.y = fmaxf(acc[i][5] + bv1.y, 0.f);
            o1.z = fmaxf(acc[i][6] + bv1.z, 0.f);
            o1.w = fmaxf(acc[i][7] + bv1.w, 0.f);
            *(float4*)&g_h[(size_t)r * NHID + tx * 8]       = o0;
            *(float4*)&g_h[(size_t)r * NHID + tx * 8 + 4]   = o1;
            *(float4*)&g_li0[(size_t)r * NHID + tx * 8]     = o0;
            *(float4*)&g_li0[(size_t)r * NHID + tx * 8 + 4] = o1;
        }
    }

    // ---------- warp-autonomous CSR scan (no barriers, no smem) ----------
    const int lane = threadIdx.x & 31;
    const unsigned ltmask = (1u << lane) - 1u;
    for (;;) {
        int row = 0;
        if (lane == 0) row = atomicAdd(&g_ctr, 1);
        row = __shfl_sync(~0u, row, 0);
        if (row >= NN) break;

        const uint4* __restrict__ r4 = (const uint4*)(adj + (size_t)row * NN);
        int* __restrict__ crow = &g_cols[row * CAP];
        int cnt = 0;

#pragma unroll 1
        for (int p = 0; p < 8; p++) {
            uint4 c[8];
            const int cb = p * 256;
#pragma unroll
            for (int u = 0; u < 8; u++) {
                const int ch = cb + u * 32 + lane;
                if (ch < NCHUNK) c[u] = r4[ch];
                else             c[u] = make_uint4(0u, 0u, 0u, 0u);
            }
#pragma unroll
            for (int u = 0; u < 8; u++) {
                const unsigned oc = (c[u].x | c[u].y) | (c[u].z | c[u].w);
                const unsigned any = __ballot_sync(~0u, oc != 0u);
                if (any) {
                    const int col0 = (cb + u * 32 + lane) * 4;
                    const unsigned bx = __ballot_sync(~0u, c[u].x != 0u);
                    const unsigned by = __ballot_sync(~0u, c[u].y != 0u);
                    const unsigned bz = __ballot_sync(~0u, c[u].z != 0u);
                    const unsigned bw = __ballot_sync(~0u, c[u].w != 0u);
                    const int nx = __popc(bx), ny = __popc(by), nz2 = __popc(bz);
                    int pos;
                    if (c[u].x) { pos = cnt + __popc(bx & ltmask);                 if (pos < CAP) crow[pos] = col0 + 0; }
                    if (c[u].y) { pos = cnt + nx + __popc(by & ltmask);            if (pos < CAP) crow[pos] = col0 + 1; }
                    if (c[u].z) { pos = cnt + nx + ny + __popc(bz & ltmask);       if (pos < CAP) crow[pos] = col0 + 2; }
                    if (c[u].w) { pos = cnt + nx + ny + nz2 + __popc(bw & ltmask); if (pos < CAP) crow[pos] = col0 + 3; }
                    cnt += nx + ny + nz2 + __popc(bw);
                }
            }
        }
        if (lane == 0) g_nnz[row] = (cnt < CAP) ? cnt : CAP;
    }
}

// ============================================================
// Fused: Pseudo = h@W1+b1, label injection (count-based, dup-safe),
// softmax -> g_yhat, Pseudo -> output. 4 rows per block, 64 threads.
// ============================================================
__global__ void __launch_bounds__(64) k_pseudo_sm(
        const float* __restrict__ W1, const float* __restrict__ b1,
        const int* __restrict__ idx, const float* __restrict__ y,
        float* __restrict__ out_pseudo) {
    const int base = blockIdx.x * 4, t = threadIdx.x;
    __shared__ __align__(16) float sh[4 * NHID];
    __shared__ float sred[4 * NCLS];
    __shared__ float smx[4], ssum[4];
    __shared__ int scnt[4];
    if (t < 4) scnt[t] = 0;
    const float4* hp = (const float4*)&g_h[(size_t)base * NHID];
    ((float4*)sh)[t]      = hp[t];
    ((float4*)sh)[t + 64] = hp[t + 64];
    __syncthreads();

    const float b = b1[t];
    float a0 = b, a1 = b, a2 = b, a3 = b;
#pragma unroll 8
    for (int k = 0; k < NHID; k++) {
        const float w = W1[k * NCLS + t];
        a0 += sh[k] * w;
        a1 += sh[NHID + k] * w;
        a2 += sh[2 * NHID + k] * w;
        a3 += sh[3 * NHID + k] * w;
    }
    for (int e = t; e < 500; e += 64) {
        const int v = idx[e] - base;
        if ((unsigned)v < 4u) atomicAdd(&scnt[v], 1);
    }
    __syncthreads();
    if (scnt[0]) a0 += 0.1f * scnt[0] * y[(size_t)(base + 0) * NCLS + t];
    if (scnt[1]) a1 += 0.1f * scnt[1] * y[(size_t)(base + 1) * NCLS + t];
    if (scnt[2]) a2 += 0.1f * scnt[2] * y[(size_t)(base + 2) * NCLS + t];
    if (scnt[3]) a3 += 0.1f * scnt[3] * y[(size_t)(base + 3) * NCLS + t];

    out_pseudo[(size_t)(base + 0) * NCLS + t] = a0;
    out_pseudo[(size_t)(base + 1) * NCLS + t] = a1;
    out_pseudo[(size_t)(base + 2) * NCLS + t] = a2;
    out_pseudo[(size_t)(base + 3) * NCLS + t] = a3;
    sred[t] = a0; sred[NCLS + t] = a1; sred[2 * NCLS + t] = a2; sred[3 * NCLS + t] = a3;
    __syncthreads();

    const int warp = t >> 5, lane = t & 31;
#pragma unroll
    for (int rr = 0; rr < 2; rr++) {
        const int r = warp * 2 + rr;
        float m = fmaxf(sred[r * NCLS + lane], sred[r * NCLS + lane + 32]);
#pragma unroll
        for (int o = 16; o; o >>= 1) m = fmaxf(m, __shfl_xor_sync(~0u, m, o));
        float s = expf(sred[r * NCLS + lane] - m) + expf(sred[r * NCLS + lane + 32] - m);
#pragma unroll
        for (int o = 16; o; o >>= 1) s += __shfl_xor_sync(~0u, s, o);
        if (lane == 0) { smx[r] = m; ssum[r] = 1.f / s; }
    }
    __syncthreads();
    g_yhat[(size_t)(base + 0) * NCLS + t] = expf(a0 - smx[0]) * ssum[0];
    g_yhat[(size_t)(base + 1) * NCLS + t] = expf(a1 - smx[1]) * ssum[1];
    g_yhat[(size_t)(base + 2) * NCLS + t] = expf(a2 - smx[2]) * ssum[2];
    g_yhat[(size_t)(base + 3) * NCLS + t] = expf(a3 - smx[3]) * ssum[3];
}

// ============================================================
// Layer 1, fused (warp per row, 4 rows / 128-thr block):
//  A: w_e = dot(yhat_i,yhat_j) (unroll-4), normalize (0.9/L1) -> smem + g_w
//  B: li1 = L2norm( sum w_e*li0[j] + 0.1*h0 )   (unroll-4 gather)
// ============================================================
__global__ void __launch_bounds__(128) k_prop1() {
    const int w    = threadIdx.x >> 5;
    const int lane = threadIdx.x & 31;
    const int i    = blockIdx.x * 4 + w;
    __shared__ int   sj[4][CAP];
    __shared__ float sw[4][CAP];

    const int nnz = g_nnz[i];
    int* jrow = sj[w];
    float* wrow = sw[w];
    for (int e = lane; e < nnz; e += 32) jrow[e] = g_cols[i * CAP + e];
    __syncwarp();

    // --- phase A: edge dots (4 gathers in flight) ---
    const float2 ya = ((const float2*)(g_yhat + (size_t)i * NCLS))[lane];
    int e = 0;
    for (; e + 4 <= nnz; e += 4) {
        const float2 v0 = ((const float2*)(g_yhat + (size_t)jrow[e]     * NCLS))[lane];
        const float2 v1 = ((const float2*)(g_yhat + (size_t)jrow[e + 1] * NCLS))[lane];
        const float2 v2 = ((const float2*)(g_yhat + (size_t)jrow[e + 2] * NCLS))[lane];
        const float2 v3 = ((const float2*)(g_yhat + (size_t)jrow[e + 3] * NCLS))[lane];
        float p0 = ya.x * v0.x + ya.y * v0.y;
        float p1 = ya.x * v1.x + ya.y * v1.y;
        float p2 = ya.x * v2.x + ya.y * v2.y;
        float p3 = ya.x * v3.x + ya.y * v3.y;
#pragma unroll
        for (int o = 16; o; o >>= 1) {
            p0 += __shfl_xor_sync(~0u, p0, o);
            p1 += __shfl_xor_sync(~0u, p1, o);
            p2 += __shfl_xor_sync(~0u, p2, o);
            p3 += __shfl_xor_sync(~0u, p3, o);
        }
        if (lane == 0) { wrow[e] = p0; wrow[e + 1] = p1; wrow[e + 2] = p2; wrow[e + 3] = p3; }
    }
    for (; e < nnz; e++) {
        const float2 v0 = ((const float2*)(g_yhat + (size_t)jrow[e] * NCLS))[lane];
        float p0 = ya.x * v0.x + ya.y * v0.y;
#pragma unroll
        for (int o = 16; o; o >>= 1) p0 += __shfl_xor_sync(~0u, p0, o);
        if (lane == 0) wrow[e] = p0;
    }
    __syncwarp();
    float s = 0.f;
    for (int q = lane; q < nnz; q += 32) s += wrow[q];
#pragma unroll
    for (int o = 16; o; o >>= 1) s += __shfl_xor_sync(~0u, s, o);
    const float scale = 0.9f / fmaxf(s, 1e-12f);
    for (int q = lane; q < nnz; q += 32) {
        const float v = wrow[q] * scale;
        wrow[q] = v;
        g_w[i * CAP + q] = v;        // reused by layer 2
    }
    __syncwarp();

    // --- phase B: gather li0 -> li1 ---
    const float4 h4 = ((const float4*)(g_h + (size_t)i * NHID))[lane];
    float4 A0 = make_float4(0.1f * h4.x, 0.1f * h4.y, 0.1f * h4.z, 0.1f * h4.w);
    float4 A1 = make_float4(0.f, 0.f, 0.f, 0.f);
    float4 A2 = make_float4(0.f, 0.f, 0.f, 0.f);
    float4 A3 = make_float4(0.f, 0.f, 0.f, 0.f);
    e = 0;
    for (; e + 4 <= nnz; e += 4) {
        const float w0 = wrow[e],     w1 = wrow[e + 1];
        const float w2 = wrow[e + 2], w3 = wrow[e + 3];
        const float4 v0 = ((const float4*)(g_li0 + (size_t)jrow[e]     * NHID))[lane];
        const float4 v1 = ((const float4*)(g_li0 + (size_t)jrow[e + 1] * NHID))[lane];
        const float4 v2 = ((const float4*)(g_li0 + (size_t)jrow[e + 2] * NHID))[lane];
        const float4 v3 = ((const float4*)(g_li0 + (size_t)jrow[e + 3] * NHID))[lane];
        A0.x += w0 * v0.x; A0.y += w0 * v0.y; A0.z += w0 * v0.z; A0.w += w0 * v0.w;
        A1.x += w1 * v1.x; A1.y += w1 * v1.y; A1.z += w1 * v1.z; A1.w += w1 * v1.w;
        A2.x += w2 * v2.x; A2.y += w2 * v2.y; A2.z += w2 * v2.z; A2.w += w2 * v2.w;
        A3.x += w3 * v3.x; A3.y += w3 * v3.y; A3.z += w3 * v3.z; A3.w += w3 * v3.w;
    }
    for (; e < nnz; e++) {
        const float w0 = wrow[e];
        const float4 v0 = ((const float4*)(g_li0 + (size_t)jrow[e] * NHID))[lane];
        A0.x += w0 * v0.x; A0.y += w0 * v0.y; A0.z += w0 * v0.z; A0.w += w0 * v0.w;
    }
    float4 acc = make_float4(A0.x + A1.x + A2.x + A3.x, A0.y + A1.y + A2.y + A3.y,
                             A0.z + A1.z + A2.z + A3.z, A0.w + A1.w + A2.w + A3.w);
    float sq = acc.x * acc.x + acc.y * acc.y + acc.z * acc.z + acc.w * acc.w;
#pragma unroll
    for (int o = 16; o; o >>= 1) sq += __shfl_xor_sync(~0u, sq, o);
    const float inv = 1.f / fmaxf(sqrtf(sq), 1e-12f);
    acc.x *= inv; acc.y *= inv; acc.z *= inv; acc.w *= inv;
    ((float4*)(g_li1 + (size_t)i * NHID))[lane] = acc;
}

// ============================================================
// Layer 2 gather + fused out = log_softmax(li @ W2 + b2).
// Warp per row, 4 rows / 128-thr block. li never hits DRAM.
// Last duty: reset g_ctr for the next graph replay.
// ============================================================
__global__ void __launch_bounds__(128) k_gather_out(
        const float* __restrict__ W2, const float* __restrict__ b2,
        float* __restrict__ out) {
    const int w    = threadIdx.x >> 5;
    const int lane = threadIdx.x & 31;
    const int i    = blockIdx.x * 4 + w;
    __shared__ float sli[4][132];
    const int nnz  = g_nnz[i];
    const int*   __restrict__ cols = &g_cols[i * CAP];
    const float* __restrict__ wts  = &g_w[i * CAP];

    const float4 h4 = ((const float4*)(g_h + (size_t)i * NHID))[lane];
    float4 A0 = make_float4(0.1f * h4.x, 0.1f * h4.y, 0.1f * h4.z, 0.1f * h4.w);
    float4 A1 = make_float4(0.f, 0.f, 0.f, 0.f);
    float4 A2 = make_float4(0.f, 0.f, 0.f, 0.f);
    float4 A3 = make_float4(0.f, 0.f, 0.f, 0.f);
    int e = 0;
    for (; e + 4 <= nnz; e += 4) {
        const int j0 = cols[e], j1 = cols[e + 1], j2 = cols[e + 2], j3 = cols[e + 3];
        const float w0 = wts[e], w1 = wts[e + 1], w2 = wts[e + 2], w3 = wts[e + 3];
        const float4 v0 = ((const float4*)(g_li1 + (size_t)j0 * NHID))[lane];
        const float4 v1 = ((const float4*)(g_li1 + (size_t)j1 * NHID))[lane];
        const float4 v2 = ((const float4*)(g_li1 + (size_t)j2 * NHID))[lane];
        const float4 v3 = ((const float4*)(g_li1 + (size_t)j3 * NHID))[lane];
        A0.x += w0 * v0.x; A0.y += w0 * v0.y; A0.z += w0 * v0.z; A0.w += w0 * v0.w;
        A1.x += w1 * v1.x; A1.y += w1 * v1.y; A1.z += w1 * v1.z; A1.w += w1 * v1.w;
        A2.x += w2 * v2.x; A2.y += w2 * v2.y; A2.z += w2 * v2.z; A2.w += w2 * v2.w;
        A3.x += w3 * v3.x; A3.y += w3 * v3.y; A3.z += w3 * v3.z; A3.w += w3 * v3.w;
    }
    for (; e < nnz; e++) {
        const float w0 = wts[e];
        const float4 v0 = ((const float4*)(g_li1 + (size_t)cols[e] * NHID))[lane];
        A0.x += w0 * v0.x; A0.y += w0 * v0.y; A0.z += w0 * v0.z; A0.w += w0 * v0.w;
    }
    float4 acc = make_float4(A0.x + A1.x + A2.x + A3.x, A0.y + A1.y + A2.y + A3.y,
                             A0.z + A1.z + A2.z + A3.z, A0.w + A1.w + A2.w + A3.w);
    float sq = acc.x * acc.x + acc.y * acc.y + acc.z * acc.z + acc.w * acc.w;
#pragma unroll
    for (int o = 16; o; o >>= 1) sq += __shfl_xor_sync(~0u, sq, o);
    const float inv = 1.f / fmaxf(sqrtf(sq), 1e-12f);
    acc.x *= inv; acc.y *= inv; acc.z *= inv; acc.w *= inv;

    // stage li row in smem; W2 GEMV via broadcast reads
    *(float4*)&sli[w][lane * 4] = acc;
    __syncwarp();
    float v0 = b2[lane], v1 = b2[lane + 32];
#pragma unroll 4
    for (int k = 0; k < NHID; k++) {
        const float lv = sli[w][k];
        v0 += lv * W2[k * NCLS + lane];
        v1 += lv * W2[k * NCLS + lane + 32];
    }
    float m = fmaxf(v0, v1);
#pragma unroll
    for (int o = 16; o; o >>= 1) m = fmaxf(m, __shfl_xor_sync(~0u, m, o));
    float sm = expf(v0 - m) + expf(v1 - m);
#pragma unroll
    for (int o = 16; o; o >>= 1) sm += __shfl_xor_sync(~0u, sm, o);
    const float ls = logf(sm);
    out[(size_t)i * NCLS + lane]      = v0 - m - ls;
    out[(size_t)i * NCLS + lane + 32] = v1 - m - ls;

    if (blockIdx.x == 0 && threadIdx.x == 0) g_ctr = 0;   // replay-safe reset
}

// ============================================================
extern "C" void kernel_launch(void* const* d_in, const int* in_sizes, int n_in,
                              void* d_out, int out_size) {
    const float* x   = (const float*)d_in[0];
    const float* adj = (const float*)d_in[1];
    const float* y   = (const float*)d_in[2];
    const int*   idx = (const int*)  d_in[3];
    const float* W0  = (const float*)d_in[4];
    const float* b0  = (const float*)d_in[5];
    const float* W1  = (const float*)d_in[6];
    const float* b1  = (const float*)d_in[7];
    const float* W2  = (const float*)d_in[8];
    const float* b2  = (const float*)d_in[9];
    (void)in_sizes; (void)n_in; (void)out_size;

    float* out_logsm  = (float*)d_out;                       // [8000,64]
    float* out_pseudo = (float*)d_out + (size_t)NN * NCLS;   // [8000,64]

    k_main<<<NBLK, 256>>>(x, W0, b0, adj);           // GEMM + warp-level scan
    k_pseudo_sm<<<NN / 4, 64>>>(W1, b1, idx, y, out_pseudo);
    k_prop1<<<NN / 4, 128>>>();                      // weights + li0 -> li1
    k_gather_out<<<NN / 4, 128>>>(W2, b2, out_logsm);  // li1 -> out (+ctr reset)
}

// round 17
// speedup vs baseline: 1.2810x; 1.0091x over previous
#include <cuda_runtime.h>

#define NN      8000
#define NFEATD  512
#define NHID    128
#define NCLS    64
#define CAP     128
#define NCHUNK  2000   // NN/4 uint4 chunks per adj row
#define NBLK    444    // 3 blocks/SM * 148 SMs
#define NGEMM   125    // GEMM tile blocks (join scan afterwards)
#define PADA    65     // transposed-A smem pad (scalar LDS, low conflict)

// ---- persistent scratch (no allocs allowed) ----
__device__ float g_h[NN * NHID];        // h = relu(xW0+b0) (== h0 == li0)
__device__ float g_li1[NN * NHID];
__device__ float g_yhat[NN * NCLS];
__device__ float g_w[NN * CAP];         // normalized edge weights (incl. 0.9/L1)
__device__ int   g_cols[NN * CAP];
__device__ int   g_nnz[NN];
__device__ int   g_ctr;                 // row-steal counter; ends every launch at 0

// ============================================================
// k_main: blocks [0,NGEMM) do one h-GEMM tile, then join the scan.
// Scan = warp-autonomous: steal row, stream 8 uint4/lane (__ldcs),
// compact via ballot/popc. No barriers, no smem in scan path.
// ============================================================
#define SM_AS   (2 * 16 * 65)
#define SM_BS   (2 * 16 * 128)

__global__ void __launch_bounds__(256, 3) k_main(
        const float* __restrict__ x,  const float* __restrict__ W0,
        const float* __restrict__ b0, const float* __restrict__ adj) {
    __shared__ __align__(16) float smem[SM_AS + SM_BS];

    if (blockIdx.x < NGEMM) {
        const int tid = threadIdx.x;
        const int tx = tid & 15, ty = tid >> 4;
        const int br = blockIdx.x * 64;
        float* As = smem;
        float* Bs = smem + SM_AS;

        const int ar = tid >> 2;
        const int ak = (tid & 3) * 4;
        const int bk = tid >> 5;
        const int bc = (tid & 31) * 4;

        float4 a_r, b_r0, b_r1;
        a_r  = *(const float4*)&x[(size_t)(br + ar) * NFEATD + ak];
        b_r0 = *(const float4*)&W0[(size_t)(bk)     * NHID + bc];
        b_r1 = *(const float4*)&W0[(size_t)(bk + 8) * NHID + bc];
        As[(0 + ak + 0) * 65 + ar] = a_r.x;
        As[(0 + ak + 1) * 65 + ar] = a_r.y;
        As[(0 + ak + 2) * 65 + ar] = a_r.z;
        As[(0 + ak + 3) * 65 + ar] = a_r.w;
        *(float4*)&Bs[(0 + bk)     * 128 + bc] = b_r0;
        *(float4*)&Bs[(0 + bk + 8) * 128 + bc] = b_r1;
        __syncthreads();

        float acc[4][8];
#pragma unroll
        for (int i = 0; i < 4; i++)
#pragma unroll
            for (int j = 0; j < 8; j++) acc[i][j] = 0.f;

        for (int kt = 0; kt < 32; kt++) {
            const int cur = (kt & 1) * 16, nxt = ((kt + 1) & 1) * 16;
            if (kt < 31) {
                const int k0 = (kt + 1) * 16;
                a_r  = *(const float4*)&x[(size_t)(br + ar) * NFEATD + k0 + ak];
                b_r0 = *(const float4*)&W0[(size_t)(k0 + bk)     * NHID + bc];
                b_r1 = *(const float4*)&W0[(size_t)(k0 + bk + 8) * NHID + bc];
            }
#pragma unroll
            for (int kk = 0; kk < 16; kk++) {
                float ra[4], rb[8];
#pragma unroll
                for (int i = 0; i < 4; i++) ra[i] = As[(cur + kk) * 65 + ty * 4 + i];
                *(float4*)&rb[0] = *(float4*)&Bs[(cur + kk) * 128 + tx * 8];
                *(float4*)&rb[4] = *(float4*)&Bs[(cur + kk) * 128 + tx * 8 + 4];
#pragma unroll
                for (int i = 0; i < 4; i++)
#pragma unroll
                    for (int j = 0; j < 8; j++) acc[i][j] += ra[i] * rb[j];
            }
            if (kt < 31) {
                As[(nxt + ak + 0) * 65 + ar] = a_r.x;
                As[(nxt + ak + 1) * 65 + ar] = a_r.y;
                As[(nxt + ak + 2) * 65 + ar] = a_r.z;
                As[(nxt + ak + 3) * 65 + ar] = a_r.w;
                *(float4*)&Bs[(nxt + bk)     * 128 + bc] = b_r0;
                *(float4*)&Bs[(nxt + bk + 8) * 128 + bc] = b_r1;
            }
            __syncthreads();
        }

        const float4 bv0 = *(const float4*)&b0[tx * 8];
        const float4 bv1 = *(const float4*)&b0[tx * 8 + 4];
#pragma unroll
        for (int i = 0; i < 4; i++) {
            const int r = br + ty * 4 + i;
            float4 o0, o1;
            o0.x = fmaxf(acc[i][0] + bv0.x, 0.f);
            o0.y = fmaxf(acc[i][1] + bv0.y, 0.f);
            o0.z = fmaxf(acc[i][2] + bv0.z, 0.f);
            o0.w = fmaxf(acc[i][3] + bv0.w, 0.f);
            o1.x = fmaxf(acc[i][4] + bv1.x, 0.f);
            o1.y = fmaxf(acc[i][5] + bv1.y, 0.f);
            o1.z = fmaxf(acc[i][6] + bv1.z, 0.f);
            o1.w = fmaxf(acc[i][7] + bv1.w, 0.f);
            *(float4*)&g_h[(size_t)r * NHID + tx * 8]     = o0;
            *(float4*)&g_h[(size_t)r * NHID + tx * 8 + 4] = o1;
        }
    }

    // ---------- warp-autonomous CSR scan (no barriers, no smem) ----------
    const int lane = threadIdx.x & 31;
    const unsigned ltmask = (1u << lane) - 1u;
    for (;;) {
        int row = 0;
        if (lane == 0) row = atomicAdd(&g_ctr, 1);
        row = __shfl_sync(~0u, row, 0);
        if (row >= NN) break;

        const uint4* __restrict__ r4 = (const uint4*)(adj + (size_t)row * NN);
        int* __restrict__ crow = &g_cols[row * CAP];
        int cnt = 0;

#pragma unroll 1
        for (int p = 0; p < 8; p++) {
            uint4 c[8];
            const int cb = p * 256;
#pragma unroll
            for (int u = 0; u < 8; u++) {
                const int ch = cb + u * 32 + lane;
                if (ch < NCHUNK) c[u] = __ldcs(&r4[ch]);
                else             c[u] = make_uint4(0u, 0u, 0u, 0u);
            }
#pragma unroll
            for (int u = 0; u < 8; u++) {
                const unsigned oc = (c[u].x | c[u].y) | (c[u].z | c[u].w);
                const unsigned any = __ballot_sync(~0u, oc != 0u);
                if (any) {
                    const int col0 = (cb + u * 32 + lane) * 4;
                    const unsigned bx = __ballot_sync(~0u, c[u].x != 0u);
                    const unsigned by = __ballot_sync(~0u, c[u].y != 0u);
                    const unsigned bz = __ballot_sync(~0u, c[u].z != 0u);
                    const unsigned bw = __ballot_sync(~0u, c[u].w != 0u);
                    const int nx = __popc(bx), ny = __popc(by), nz2 = __popc(bz);
                    int pos;
                    if (c[u].x) { pos = cnt + __popc(bx & ltmask);                 if (pos < CAP) crow[pos] = col0 + 0; }
                    if (c[u].y) { pos = cnt + nx + __popc(by & ltmask);            if (pos < CAP) crow[pos] = col0 + 1; }
                    if (c[u].z) { pos = cnt + nx + ny + __popc(bz & ltmask);       if (pos < CAP) crow[pos] = col0 + 2; }
                    if (c[u].w) { pos = cnt + nx + ny + nz2 + __popc(bw & ltmask); if (pos < CAP) crow[pos] = col0 + 3; }
                    cnt += nx + ny + nz2 + __popc(bw);
                }
            }
        }
        if (lane == 0) g_nnz[row] = (cnt < CAP) ? cnt : CAP;
    }
}

// ============================================================
// Pseudo = h@W1+b1 (tiled GEMM 64x64, K=128) + injection + softmax.
// A transposed in smem (pad 65); W1 read from global (L1-resident).
// ============================================================
__global__ void __launch_bounds__(256) k_pseudo_gemm(
        const float* __restrict__ W1, const float* __restrict__ b1,
        const int* __restrict__ idx, const float* __restrict__ y,
        float* __restrict__ out_pseudo) {
    __shared__ __align__(16) float Ah[NHID * PADA];   // 33.3 KB
    __shared__ int scnt[64];
    float* P = Ah;                                    // overlay after GEMM
    const int tid = threadIdx.x;
    const int br  = blockIdx.x * 64;

    if (tid < 64) scnt[tid] = 0;
#pragma unroll
    for (int l = 0; l < 8; l++) {
        const int ch = tid + l * 256;      // 2048 chunks = 64 rows x 32 kq
        const int row = ch >> 5, kq = ch & 31;
        const float4 v = *(const float4*)&g_h[(size_t)(br + row) * NHID + kq * 4];
        Ah[(kq * 4 + 0) * PADA + row] = v.x;
        Ah[(kq * 4 + 1) * PADA + row] = v.y;
        Ah[(kq * 4 + 2) * PADA + row] = v.z;
        Ah[(kq * 4 + 3) * PADA + row] = v.w;
    }
    __syncthreads();
    for (int e = tid; e < 500; e += 256) {
        const int v = idx[e] - br;
        if ((unsigned)v < 64u) atomicAdd(&scnt[v], 1);
    }

    const int tx = tid & 15, ty = tid >> 4;
    float acc[4][4];
#pragma unroll
    for (int i = 0; i < 4; i++)
#pragma unroll
        for (int j = 0; j < 4; j++) acc[i][j] = 0.f;

#pragma unroll 4
    for (int k = 0; k < NHID; k++) {
        const float4 rb = *(const float4*)&W1[k * NCLS + tx * 4];
        float ra[4];
#pragma unroll
        for (int i = 0; i < 4; i++) ra[i] = Ah[k * PADA + ty * 4 + i];
#pragma unroll
        for (int i = 0; i < 4; i++) {
            acc[i][0] += ra[i] * rb.x;
            acc[i][1] += ra[i] * rb.y;
            acc[i][2] += ra[i] * rb.z;
            acc[i][3] += ra[i] * rb.w;
        }
    }
    __syncthreads();   // Ah reads done; scnt adds visible

    const float4 bv = *(const float4*)&b1[tx * 4];
#pragma unroll
    for (int i = 0; i < 4; i++) {
        const int r = ty * 4 + i;
        float4 p = make_float4(acc[i][0] + bv.x, acc[i][1] + bv.y,
                               acc[i][2] + bv.z, acc[i][3] + bv.w);
        const int cnt = scnt[r];
        if (cnt) {
            const float4 yv = *(const float4*)&y[(size_t)(br + r) * NCLS + tx * 4];
            const float f = 0.1f * cnt;
            p.x += f * yv.x; p.y += f * yv.y; p.z += f * yv.z; p.w += f * yv.w;
        }
        *(float4*)&out_pseudo[(size_t)(br + r) * NCLS + tx * 4] = p;
        *(float4*)&P[r * 68 + tx * 4] = p;
    }
    __syncthreads();

    const int w = tid >> 5, lane = tid & 31;
#pragma unroll
    for (int rr = 0; rr < 8; rr++) {
        const int row = w * 8 + rr;
        const float v0 = P[row * 68 + lane];
        const float v1 = P[row * 68 + lane + 32];
        float m = fmaxf(v0, v1);
#pragma unroll
        for (int o = 16; o; o >>= 1) m = fmaxf(m, __shfl_xor_sync(~0u, m, o));
        const float e0 = expf(v0 - m), e1 = expf(v1 - m);
        float s = e0 + e1;
#pragma unroll
        for (int o = 16; o; o >>= 1) s += __shfl_xor_sync(~0u, s, o);
        const float inv = 1.f / s;
        g_yhat[(size_t)(br + row) * NCLS + lane]      = e0 * inv;
        g_yhat[(size_t)(br + row) * NCLS + lane + 32] = e1 * inv;
    }
}

// ============================================================
// Layer 1, fused (warp per row, 4 rows / 128-thr block):
//  A: w_e = dot(yhat_i,yhat_j) (unroll-4), normalize -> smem + g_w
//  B: li1 = L2norm( sum w_e*h[j] + 0.1*h[i] )   (unroll-4 gather; li0==h)
// ============================================================
__global__ void __launch_bounds__(128) k_prop1() {
    const int w    = threadIdx.x >> 5;
    const int lane = threadIdx.x & 31;
    const int i    = blockIdx.x * 4 + w;
    __shared__ int   sj[4][CAP];
    __shared__ float sw[4][CAP];

    const int nnz = g_nnz[i];
    int* jrow = sj[w];
    float* wrow = sw[w];
    for (int e = lane; e < nnz; e += 32) jrow[e] = g_cols[i * CAP + e];
    __syncwarp();

    const float2 ya = ((const float2*)(g_yhat + (size_t)i * NCLS))[lane];
    int e = 0;
    for (; e + 4 <= nnz; e += 4) {
        const float2 v0 = ((const float2*)(g_yhat + (size_t)jrow[e]     * NCLS))[lane];
        const float2 v1 = ((const float2*)(g_yhat + (size_t)jrow[e + 1] * NCLS))[lane];
        const float2 v2 = ((const float2*)(g_yhat + (size_t)jrow[e + 2] * NCLS))[lane];
        const float2 v3 = ((const float2*)(g_yhat + (size_t)jrow[e + 3] * NCLS))[lane];
        float p0 = ya.x * v0.x + ya.y * v0.y;
        float p1 = ya.x * v1.x + ya.y * v1.y;
        float p2 = ya.x * v2.x + ya.y * v2.y;
        float p3 = ya.x * v3.x + ya.y * v3.y;
#pragma unroll
        for (int o = 16; o; o >>= 1) {
            p0 += __shfl_xor_sync(~0u, p0, o);
            p1 += __shfl_xor_sync(~0u, p1, o);
            p2 += __shfl_xor_sync(~0u, p2, o);
            p3 += __shfl_xor_sync(~0u, p3, o);
        }
        if (lane == 0) { wrow[e] = p0; wrow[e + 1] = p1; wrow[e + 2] = p2; wrow[e + 3] = p3; }
    }
    for (; e < nnz; e++) {
        const float2 v0 = ((const float2*)(g_yhat + (size_t)jrow[e] * NCLS))[lane];
        float p0 = ya.x * v0.x + ya.y * v0.y;
#pragma unroll
        for (int o = 16; o; o >>= 1) p0 += __shfl_xor_sync(~0u, p0, o);
        if (lane == 0) wrow[e] = p0;
    }
    __syncwarp();
    float s = 0.f;
    for (int q = lane; q < nnz; q += 32) s += wrow[q];
#pragma unroll
    for (int o = 16; o; o >>= 1) s += __shfl_xor_sync(~0u, s, o);
    const float scale = 0.9f / fmaxf(s, 1e-12f);
    for (int q = lane; q < nnz; q += 32) {
        const float v = wrow[q] * scale;
        wrow[q] = v;
        g_w[i * CAP + q] = v;
    }
    __syncwarp();

    const float4 h4 = ((const float4*)(g_h + (size_t)i * NHID))[lane];
    float4 A0 = make_float4(0.1f * h4.x, 0.1f * h4.y, 0.1f * h4.z, 0.1f * h4.w);
    float4 A1 = make_float4(0.f, 0.f, 0.f, 0.f);
    float4 A2 = make_float4(0.f, 0.f, 0.f, 0.f);
    float4 A3 = make_float4(0.f, 0.f, 0.f, 0.f);
    e = 0;
    for (; e + 4 <= nnz; e += 4) {
        const float w0 = wrow[e],     w1 = wrow[e + 1];
        const float w2 = wrow[e + 2], w3 = wrow[e + 3];
        const float4 v0 = ((const float4*)(g_h + (size_t)jrow[e]     * NHID))[lane];
        const float4 v1 = ((const float4*)(g_h + (size_t)jrow[e + 1] * NHID))[lane];
        const float4 v2 = ((const float4*)(g_h + (size_t)jrow[e + 2] * NHID))[lane];
        const float4 v3 = ((const float4*)(g_h + (size_t)jrow[e + 3] * NHID))[lane];
        A0.x += w0 * v0.x; A0.y += w0 * v0.y; A0.z += w0 * v0.z; A0.w += w0 * v0.w;
        A1.x += w1 * v1.x; A1.y += w1 * v1.y; A1.z += w1 * v1.z; A1.w += w1 * v1.w;
        A2.x += w2 * v2.x; A2.y += w2 * v2.y; A2.z += w2 * v2.z; A2.w += w2 * v2.w;
        A3.x += w3 * v3.x; A3.y += w3 * v3.y; A3.z += w3 * v3.z; A3.w += w3 * v3.w;
    }
    for (; e < nnz; e++) {
        const float w0 = wrow[e];
        const float4 v0 = ((const float4*)(g_h + (size_t)jrow[e] * NHID))[lane];
        A0.x += w0 * v0.x; A0.y += w0 * v0.y; A0.z += w0 * v0.z; A0.w += w0 * v0.w;
    }
    float4 acc = make_float4(A0.x + A1.x + A2.x + A3.x, A0.y + A1.y + A2.y + A3.y,
                             A0.z + A1.z + A2.z + A3.z, A0.w + A1.w + A2.w + A3.w);
    float sq = acc.x * acc.x + acc.y * acc.y + acc.z * acc.z + acc.w * acc.w;
#pragma unroll
    for (int o = 16; o; o >>= 1) sq += __shfl_xor_sync(~0u, sq, o);
    const float inv = 1.f / fmaxf(sqrtf(sq), 1e-12f);
    acc.x *= inv; acc.y *= inv; acc.z *= inv; acc.w *= inv;
    ((float4*)(g_li1 + (size_t)i * NHID))[lane] = acc;
}

// ============================================================
// k_final: per-block gather of 64 li rows (warp-per-row, into
// transposed smem) -> tiled GEMM @W2 -> log_softmax -> out.
// li never touches DRAM. Resets g_ctr for next graph replay.
// ============================================================
__global__ void __launch_bounds__(256) k_final(
        const float* __restrict__ W2, const float* __restrict__ b2,
        float* __restrict__ out) {
    __shared__ __align__(16) float Ah[NHID * PADA];   // 33.3 KB
    float* P = Ah;                                    // overlay after GEMM
    const int tid = threadIdx.x;
    const int br  = blockIdx.x * 64;
    const int w = tid >> 5, lane = tid & 31;

    // ---- phase 1: gather 8 rows per warp into transposed smem ----
    for (int rr = 0; rr < 8; rr++) {
        const int r = w * 8 + rr;
        const int i = br + r;
        const int nnz = g_nnz[i];
        const int*   __restrict__ cols = &g_cols[i * CAP];
        const float* __restrict__ wts  = &g_w[i * CAP];

        const float4 h4 = ((const float4*)(g_h + (size_t)i * NHID))[lane];
        float4 A0 = make_float4(0.1f * h4.x, 0.1f * h4.y, 0.1f * h4.z, 0.1f * h4.w);
        float4 A1 = make_float4(0.f, 0.f, 0.f, 0.f);
        float4 A2 = make_float4(0.f, 0.f, 0.f, 0.f);
        float4 A3 = make_float4(0.f, 0.f, 0.f, 0.f);
        int e = 0;
        for (; e + 4 <= nnz; e += 4) {
            const int j0 = cols[e], j1 = cols[e + 1], j2 = cols[e + 2], j3 = cols[e + 3];
            const float w0 = wts[e], w1 = wts[e + 1], w2 = wts[e + 2], w3 = wts[e + 3];
            const float4 v0 = ((const float4*)(g_li1 + (size_t)j0 * NHID))[lane];
            const float4 v1 = ((const float4*)(g_li1 + (size_t)j1 * NHID))[lane];
            const float4 v2 = ((const float4*)(g_li1 + (size_t)j2 * NHID))[lane];
            const float4 v3 = ((const float4*)(g_li1 + (size_t)j3 * NHID))[lane];
            A0.x += w0 * v0.x; A0.y += w0 * v0.y; A0.z += w0 * v0.z; A0.w += w0 * v0.w;
            A1.x += w1 * v1.x; A1.y += w1 * v1.y; A1.z += w1 * v1.z; A1.w += w1 * v1.w;
            A2.x += w2 * v2.x; A2.y += w2 * v2.y; A2.z += w2 * v2.z; A2.w += w2 * v2.w;
            A3.x += w3 * v3.x; A3.y += w3 * v3.y; A3.z += w3 * v3.z; A3.w += w3 * v3.w;
        }
        for (; e < nnz; e++) {
            const float w0 = wts[e];
            const float4 v0 = ((const float4*)(g_li1 + (size_t)cols[e] * NHID))[lane];
            A0.x += w0 * v0.x; A0.y += w0 * v0.y; A0.z += w0 * v0.z; A0.w += w0 * v0.w;
        }
        float4 acc = make_float4(A0.x + A1.x + A2.x + A3.x, A0.y + A1.y + A2.y + A3.y,
                                 A0.z + A1.z + A2.z + A3.z, A0.w + A1.w + A2.w + A3.w);
        float sq = acc.x * acc.x + acc.y * acc.y + acc.z * acc.z + acc.w * acc.w;
#pragma unroll
        for (int o = 16; o; o >>= 1) sq += __shfl_xor_sync(~0u, sq, o);
        const float inv = 1.f / fmaxf(sqrtf(sq), 1e-12f);
        Ah[(lane * 4 + 0) * PADA + r] = acc.x * inv;
        Ah[(lane * 4 + 1) * PADA + r] = acc.y * inv;
        Ah[(lane * 4 + 2) * PADA + r] = acc.z * inv;
        Ah[(lane * 4 + 3) * PADA + r] = acc.w * inv;
    }
    __syncthreads();

    // ---- phase 2: GEMM [64x64, K=128] ----
    const int tx = tid & 15, ty = tid >> 4;
    float acc[4][4];
#pragma unroll
    for (int i = 0; i < 4; i++)
#pragma unroll
        for (int j = 0; j < 4; j++) acc[i][j] = 0.f;

#pragma unroll 4
    for (int k = 0; k < NHID; k++) {
        const float4 rb = *(const float4*)&W2[k * NCLS + tx * 4];
        float ra[4];
#pragma unroll
        for (int i = 0; i < 4; i++) ra[i] = Ah[k * PADA + ty * 4 + i];
#pragma unroll
        for (int i = 0; i < 4; i++) {
            acc[i][0] += ra[i] * rb.x;
            acc[i][1] += ra[i] * rb.y;
            acc[i][2] += ra[i] * rb.z;
            acc[i][3] += ra[i] * rb.w;
        }
    }
    __syncthreads();

    const float4 bv = *(const float4*)&b2[tx * 4];
#pragma unroll
    for (int i = 0; i < 4; i++) {
        const int r = ty * 4 + i;
        *(float4*)&P[r * 68 + tx * 4] = make_float4(
            acc[i][0] + bv.x, acc[i][1] + bv.y, acc[i][2] + bv.z, acc[i][3] + bv.w);
    }
    __syncthreads();

    // ---- phase 3: log_softmax per row ----
#pragma unroll
    for (int rr = 0; rr < 8; rr++) {
        const int row = w * 8 + rr;
        const float v0 = P[row * 68 + lane];
        const float v1 = P[row * 68 + lane + 32];
        float m = fmaxf(v0, v1);
#pragma unroll
        for (int o = 16; o; o >>= 1) m = fmaxf(m, __shfl_xor_sync(~0u, m, o));
        float s = expf(v0 - m) + expf(v1 - m);
#pragma unroll
        for (int o = 16; o; o >>= 1) s += __shfl_xor_sync(~0u, s, o);
        const float ls = logf(s);
        out[(size_t)(br + row) * NCLS + lane]      = v0 - m - ls;
        out[(size_t)(br + row) * NCLS + lane + 32] = v1 - m - ls;
    }

    if (blockIdx.x == 0 && tid == 0) g_ctr = 0;   // replay-safe reset
}

// ============================================================
extern "C" void kernel_launch(void* const* d_in, const int* in_sizes, int n_in,
                              void* d_out, int out_size) {
    const float* x   = (const float*)d_in[0];
    const float* adj = (const float*)d_in[1];
    const float* y   = (const float*)d_in[2];
    const int*   idx = (const int*)  d_in[3];
    const float* W0  = (const float*)d_in[4];
    const float* b0  = (const float*)d_in[5];
    const float* W1  = (const float*)d_in[6];
    const float* b1  = (const float*)d_in[7];
    const float* W2  = (const float*)d_in[8];
    const float* b2  = (const float*)d_in[9];
    (void)in_sizes; (void)n_in; (void)out_size;

    float* out_logsm  = (float*)d_out;                       // [8000,64]
    float* out_pseudo = (float*)d_out + (size_t)NN * NCLS;   // [8000,64]

    k_main<<<NBLK, 256>>>(x, W0, b0, adj);             // h-GEMM + warp scan
    k_pseudo_gemm<<<NN / 64, 256>>>(W1, b1, idx, y, out_pseudo);
    k_prop1<<<NN / 4, 128>>>();                        // weights + h -> li1
    k_final<<<NN / 64, 256>>>(W2, b2, out_logsm);      // gather+GEMM+logsoftmax
}